// round 12
// baseline (speedup 1.0000x reference)
#include <cuda_runtime.h>
#include <cuda_bf16.h>
#include <mma.h>
#include <math.h>
#include <stdint.h>

using namespace nvcuda;

// ---------------- problem constants ----------------
#define N1 3000
#define N2 2500
#define N3 2500
#define NTOT 8000
#define NPAD 8192
#define IN_F 128
#define OUT_F 64
#define HEADS 2
#define WORDS 250              // 8000/32 mask words per row

#define MROWS 128              // rows per k_att CTA
#define TJ 64                  // K per j-tile
#define NTILE_J (NTOT / TJ)    // 125

#define PSTR 72                // bf16 tile row stride (144B: conflict-free LDSM/STS)
#define CSTR 68                // f32 C tile row stride

// ---------------- device scratch ----------------
__device__ __nv_bfloat16 g_WhT[HEADS * OUT_F * NPAD];  // [head*64+o][n] bf16, 2MB
__device__ float    g_E1[HEADS * NPAD];
__device__ float    g_E2[HEADS * NPAD];
__device__ float    g_ff[HEADS * NPAD * 2];            // {F1, F2} per node
__device__ unsigned g_mask[NPAD * WORDS];              // 8MB bitmask
__device__ float    g_x2[NTOT * HEADS * OUT_F];        // 4MB

// ---------------- helpers ----------------
static __device__ __forceinline__ unsigned long long dup2(float x) {
    unsigned long long r;
    asm("mov.b64 %0, {%1, %2};" : "=l"(r) : "f"(x), "f"(x));
    return r;
}
static __device__ __forceinline__ void fma2(unsigned long long &acc,
                                            unsigned long long a, unsigned long long b) {
    asm("fma.rn.f32x2 %0, %1, %2, %0;" : "+l"(acc) : "l"(a), "l"(b));
}
static __device__ __forceinline__ float2 upk(unsigned long long v) {
    float2 f;
    asm("mov.b64 {%0, %1}, %2;" : "=f"(f.x), "=f"(f.y) : "l"(v));
    return f;
}
static __device__ __forceinline__ unsigned cvt_bf16x2(float lo, float hi) {
    unsigned r;
    asm("cvt.rn.satfinite.bf16x2.f32 %0, %1, %2;" : "=r"(r) : "f"(hi), "f"(lo));
    return r;
}

#define BAR_SYNC(id)   asm volatile("bar.sync %0, 512;"   :: "r"(id) : "memory")
#define BAR_ARRIVE(id) asm volatile("bar.arrive %0, 512;" :: "r"(id) : "memory")

// ---------------- kernel 1: per-node scalars (k_prep fused in) ----------------
__global__ void __launch_bounds__(256) k_scal(const float* __restrict__ h,
                                              const float* __restrict__ Ws,
                                              const float* __restrict__ ap) {
    __shared__ float su[2][2][IN_F];           // [head][which][f]
    const int t = threadIdx.x;

#pragma unroll
    for (int d = 0; d < 2; ++d) {
        const int id = t + 256 * d;            // 0..511
        const int hd = id >> 8, which = (id >> 7) & 1, f = id & 127;
        const float4* w = (const float4*)(Ws + hd * (IN_F * OUT_F) + f * OUT_F);
        const float4* a = (const float4*)(ap + hd * 2 * OUT_F + which * OUT_F);
        float acc = 0.f;
#pragma unroll
        for (int k = 0; k < OUT_F / 4; ++k) {
            float4 wv = w[k], av = a[k];
            acc += wv.x * av.x + wv.y * av.y + wv.z * av.z + wv.w * av.w;
        }
        su[hd][which][f] = acc;
    }
    __syncthreads();

    const int idx = blockIdx.x * 256 + t;
    if (idx >= HEADS * NTOT) return;
    const int hd = idx / NTOT, i = idx % NTOT;
    const int g = hd * NPAD + i;
    const float4* hr = (const float4*)(h + i * IN_F);
    const float4* u1 = (const float4*)(&su[hd][0][0]);
    const float4* u2 = (const float4*)(&su[hd][1][0]);
    float c = 0.f, s = 0.f;
#pragma unroll
    for (int k = 0; k < IN_F / 4; ++k) {
        float4 hv = hr[k], x = u1[k], y = u2[k];
        c += hv.x * x.x + hv.y * x.y + hv.z * x.z + hv.w * x.w;
        s += hv.x * y.x + hv.y * y.y + hv.z * y.z + hv.w * y.w;
    }
    g_E1[g] = __expf(c);
    g_E2[g] = __expf(0.2f * c);
    g_ff[g * 2]     = __expf(s);
    g_ff[g * 2 + 1] = __expf(0.2f * s);
}

// ---------------- kernel 2: WhT (bf16, transposed) = (h @ Ws)^T ----------------
__global__ void __launch_bounds__(256) k_wh(const float* __restrict__ h,
                                            const float* __restrict__ Ws) {
    extern __shared__ float wsm[];
    float* sh = wsm;                 // [k][n pad 68]
    float* sW = wsm + 128 * 68;      // [k][ho=head*64+o]
    const int tid = threadIdx.x;
    const int n0 = blockIdx.x * 64;

#pragma unroll
    for (int e = 0; e < 16; ++e) {
        const int idx = tid + 256 * e;
        const int hd = idx >> 11, rem = idx & 2047, k = rem >> 4, o4 = rem & 15;
        float4 v = ((const float4*)Ws)[idx];
        *(float4*)&sW[k * 128 + hd * 64 + o4 * 4] = v;
    }
#pragma unroll
    for (int e = 0; e < 8; ++e) {
        const int idx = tid + 256 * e;
        const int n = idx >> 5, k4 = idx & 31;
        float4 v = *(const float4*)(h + (n0 + n) * IN_F + k4 * 4);
        sh[(k4 * 4 + 0) * 68 + n] = v.x;
        sh[(k4 * 4 + 1) * 68 + n] = v.y;
        sh[(k4 * 4 + 2) * 68 + n] = v.z;
        sh[(k4 * 4 + 3) * 68 + n] = v.w;
    }
    __syncthreads();

    const int tx = tid & 15, ty = tid >> 4;     // 8 ho x 4 n per thread
    unsigned long long acc[4][4];
#pragma unroll
    for (int r = 0; r < 4; ++r)
#pragma unroll
        for (int c = 0; c < 4; ++c) acc[r][c] = 0ull;

#pragma unroll 4
    for (int k = 0; k < IN_F; ++k) {
        const float4 hv = *(const float4*)&sh[k * 68 + ty * 4];
        const ulonglong2 wA = *(const ulonglong2*)&sW[k * 128 + tx * 8];
        const ulonglong2 wB = *(const ulonglong2*)&sW[k * 128 + tx * 8 + 4];
        const float hr[4] = {hv.x, hv.y, hv.z, hv.w};
#pragma unroll
        for (int r = 0; r < 4; ++r) {
            const unsigned long long hd2 = dup2(hr[r]);
            fma2(acc[r][0], hd2, wA.x); fma2(acc[r][1], hd2, wA.y);
            fma2(acc[r][2], hd2, wB.x); fma2(acc[r][3], hd2, wB.y);
        }
    }

    float v[4][8];
#pragma unroll
    for (int r = 0; r < 4; ++r)
#pragma unroll
        for (int c = 0; c < 4; ++c) {
            float2 f = upk(acc[r][c]);
            v[r][2 * c] = f.x; v[r][2 * c + 1] = f.y;
        }
#pragma unroll
    for (int hh = 0; hh < 8; ++hh) {
        const int ho = tx * 8 + hh;
        unsigned u0 = cvt_bf16x2(v[0][hh], v[1][hh]);
        unsigned u1 = cvt_bf16x2(v[2][hh], v[3][hh]);
        *(uint2*)((char*)g_WhT + (ho * NPAD + n0 + ty * 4) * 2) = make_uint2(u0, u1);
    }
}

// ---------------- kernel 3: pack block-mask into bitmask (R8 proven version) ----
static __device__ __forceinline__ int4 mask4(
    int i, int j4,
    const int* __restrict__ A1,  const int* __restrict__ A2,  const int* __restrict__ A3,
    const int* __restrict__ A12, const int* __restrict__ A13, const int* __restrict__ A23,
    const int* __restrict__ A21, const int* __restrict__ A31, const int* __restrict__ A32) {
    const int j = j4 * 4;
    if (i < N1) {
        if (j < N1) return *(const int4*)(A1 + i * N1 + j);
        if (j < N1 + N2) return *(const int4*)(A12 + i * N2 + (j - N1));
        return *(const int4*)(A13 + i * N3 + (j - N1 - N2));
    } else if (i < N1 + N2) {
        const int ii = i - N1;
        if (j < N1) return *(const int4*)(A21 + ii * N1 + j);
        if (j < N1 + N2) return *(const int4*)(A2 + ii * N2 + (j - N1));
        return *(const int4*)(A23 + ii * N3 + (j - N1 - N2));
    } else {
        const int ii = i - N1 - N2;
        if (j < N1) return *(const int4*)(A31 + ii * N1 + j);
        if (j < N1 + N2) return *(const int4*)(A32 + ii * N2 + (j - N1));
        return *(const int4*)(A3 + ii * N3 + (j - N1 - N2));
    }
}

__global__ void __launch_bounds__(256) k_maskpack(
    const int* __restrict__ A1,  const int* __restrict__ A2,  const int* __restrict__ A3,
    const int* __restrict__ A12, const int* __restrict__ A13, const int* __restrict__ A23,
    const int* __restrict__ A21, const int* __restrict__ A31, const int* __restrict__ A32) {
    const int row  = blockIdx.x;
    const int t    = threadIdx.x;
    const int lane = t & 31;
    const unsigned gmask = 0xFFu << ((lane >> 3) << 3);
    const int shift = (lane & 7) * 4;

    int4 v[8];
#pragma unroll
    for (int it = 0; it < 8; ++it) {
        const int idx4 = it * 256 + t;           // int4 index within row (0..1999)
        if (idx4 < 2000)
            v[it] = mask4(row, idx4, A1, A2, A3, A12, A13, A23, A21, A31, A32);
    }
#pragma unroll
    for (int it = 0; it < 8; ++it) {
        const int idx4 = it * 256 + t;
        if (idx4 < 2000) {
            const int4 a = v[it];
            unsigned nib = (unsigned)(a.x > 0) | ((unsigned)(a.y > 0) << 1)
                         | ((unsigned)(a.z > 0) << 2) | ((unsigned)(a.w > 0) << 3);
            const unsigned word = __reduce_or_sync(gmask, nib << shift);
            if ((lane & 7) == 0)
                g_mask[row * WORDS + (idx4 >> 3)] = word;
        }
    }
}

// ---------------- kernel 4: warp-specialized attention (WMMA bf16) ----------------
// grid (64, 2), 512 threads. Warps 0-7 = consumers (MMA, 16x64 C tile each),
// warps 8-15 = producers (P gen 32 js/thread + B staging). Handoff via named
// barriers (ids 1,2 = full[b]; 3,4 = empty[b]), double-buffered P/B, so producer
// work (LDG + ALU) overlaps consumer MMA on every SMSP.
// p = fmaxf(E1*F1, E2*F2) masked  (exp monotone => select == max).
#define PBUF (MROWS * PSTR)            // 9216 bf16
#define BBUF (OUT_F * PSTR)            // 4608 bf16
#define ATT_SMEM ((2 * PBUF + 2 * BBUF) * 2)   // 55296 B

__global__ void __launch_bounds__(512, 1) k_att() {
    extern __shared__ char dsm[];
    __nv_bfloat16* sP[2] = {(__nv_bfloat16*)dsm, (__nv_bfloat16*)dsm + PBUF};
    __nv_bfloat16* sB[2] = {(__nv_bfloat16*)dsm + 2 * PBUF,
                            (__nv_bfloat16*)dsm + 2 * PBUF + BBUF};
    float* sC = (float*)dsm;           // alias, post-loop (128*68*4 = 34816 B)
    __shared__ float sDen[2][MROWS];

    const int head = blockIdx.y;
    const int i0   = blockIdx.x * MROWS;
    const int hb   = head * NPAD;
    const int tid  = threadIdx.x;
    const int wid  = tid >> 5;

    if (wid < 8) {
        // ================= consumer: warp wy handles rows wy*16.., all 64 cols
        const int wy = wid;
        wmma::fragment<wmma::accumulator, 16, 16, 16, float> cf[4];
#pragma unroll
        for (int n = 0; n < 4; ++n) wmma::fill_fragment(cf[n], 0.f);

#pragma unroll 1
        for (int jt = 0; jt < NTILE_J; ++jt) {
            const int b = jt & 1;
            BAR_SYNC(1 + b);                    // wait full[b]
#pragma unroll
            for (int k = 0; k < 4; ++k) {
                wmma::fragment<wmma::matrix_a, 16, 16, 16, __nv_bfloat16, wmma::row_major> a;
                wmma::load_matrix_sync(a, sP[b] + wy * 16 * PSTR + k * 16, PSTR);
#pragma unroll
                for (int n = 0; n < 4; ++n) {
                    wmma::fragment<wmma::matrix_b, 16, 16, 16, __nv_bfloat16, wmma::col_major> bf;
                    wmma::load_matrix_sync(bf, sB[b] + (n * 16) * PSTR + k * 16, PSTR);
                    wmma::mma_sync(cf[n], a, bf, cf[n]);
                }
            }
            BAR_ARRIVE(3 + b);                  // signal empty[b]
        }

        __syncthreads();                        // producers done; safe to alias
#pragma unroll
        for (int n = 0; n < 4; ++n)
            wmma::store_matrix_sync(sC + wy * 16 * CSTR + n * 16, cf[n], CSTR,
                                    wmma::mem_row_major);
    } else {
        // ================= producer: ptid 0..255 -> row r, j-half q (32 js)
        const int ptid = tid - 256;
        const int r = ptid & 127;
        const int q = ptid >> 7;                // 0,1
        const float e1i = g_E1[hb + i0 + r];
        const float e2i = g_E2[hb + i0 + r];
        const unsigned* mrow = g_mask + (i0 + r) * WORDS;
        const float4* ffp = (const float4*)(g_ff + hb * 2);
        const int jl0 = q * 32;

        // B staging: 2 consecutive 16B granules per thread
        const int g0 = ptid * 2;
        const int bo = g0 >> 3, bg = g0 & 7;
        const char* bsrc = (const char*)g_WhT + ((head * OUT_F + bo) * NPAD) * 2 + bg * 16;
        const int bdst = bo * PSTR + bg * 8;

        float dsum = 0.f;

#pragma unroll 1
        for (int jt = 0; jt < NTILE_J; ++jt) {
            const int b = jt & 1;
            const int jbase = jt * TJ;
            if (jt >= 2) BAR_SYNC(3 + b);       // wait empty[b]

            // B tile
            *(uint4*)(sB[b] + bdst)     = *(const uint4*)(bsrc + jbase * 2);
            *(uint4*)(sB[b] + bdst + 8) = *(const uint4*)(bsrc + jbase * 2 + 16);

            // P tile: 32 js -> 16 bf16x2 -> 4 STS.128
            const unsigned mw = mrow[(jbase >> 5) + q];
            const float4* f4 = ffp + ((jbase + jl0) >> 1);
            unsigned pk[16];
#pragma unroll
            for (int k2 = 0; k2 < 16; ++k2) {
                const float4 f = f4[k2];
                const float w0 = fmaxf(e1i * f.x, e2i * f.y);
                const float w1 = fmaxf(e1i * f.z, e2i * f.w);
                const float p0 = ((mw >> (2 * k2))     & 1u) ? w0 : 0.f;
                const float p1 = ((mw >> (2 * k2 + 1)) & 1u) ? w1 : 0.f;
                dsum += p0 + p1;
                pk[k2] = cvt_bf16x2(p0, p1);
            }
            uint4* d = (uint4*)(sP[b] + r * PSTR + jl0);
            d[0] = make_uint4(pk[0],  pk[1],  pk[2],  pk[3]);
            d[1] = make_uint4(pk[4],  pk[5],  pk[6],  pk[7]);
            d[2] = make_uint4(pk[8],  pk[9],  pk[10], pk[11]);
            d[3] = make_uint4(pk[12], pk[13], pk[14], pk[15]);

            BAR_ARRIVE(1 + b);                  // signal full[b]
        }

        sDen[q][r] = dsum;
        __syncthreads();                        // join consumers before alias
    }

    __syncthreads();                            // sC + sDen complete

    // epilogue: normalize, ELU, write (all 512 threads; 128 rows x 4 col-groups)
    const int row = tid >> 2, cg = tid & 3;
    if (i0 + row < NTOT) {
        const float den = sDen[0][row] + sDen[1][row];
        const float inv = 1.f / den;
        const float* src = sC + row * CSTR + cg * 16;
        float* op = g_x2 + (i0 + row) * (HEADS * OUT_F) + head * OUT_F + cg * 16;
#pragma unroll
        for (int c4 = 0; c4 < 4; ++c4) {
            float4 v = *(const float4*)(src + c4 * 4);
            float x0 = v.x * inv, x1 = v.y * inv, x2 = v.z * inv, x3 = v.w * inv;
            x0 = (x0 > 0.f) ? x0 : expm1f(x0);
            x1 = (x1 > 0.f) ? x1 : expm1f(x1);
            x2 = (x2 > 0.f) ? x2 : expm1f(x2);
            x3 = (x3 > 0.f) ? x3 : expm1f(x3);
            *(float4*)(op + c4 * 4) = make_float4(x0, x1, x2, x3);
        }
    }
}

// ---------------- kernel 5: log_softmax (128-wide) + permuted row write ----------------
__global__ void __launch_bounds__(256) k_lsm(float* __restrict__ out) {
    const int lane = threadIdx.x & 31;
    const int i = blockIdx.x * 8 + (threadIdx.x >> 5);
    float4 v = ((const float4*)(g_x2 + i * 128))[lane];
    float mx = fmaxf(fmaxf(v.x, v.y), fmaxf(v.z, v.w));
#pragma unroll
    for (int off = 16; off > 0; off >>= 1)
        mx = fmaxf(mx, __shfl_xor_sync(0xffffffffu, mx, off));
    float sum = __expf(v.x - mx) + __expf(v.y - mx) + __expf(v.z - mx) + __expf(v.w - mx);
#pragma unroll
    for (int off = 16; off > 0; off >>= 1)
        sum += __shfl_xor_sync(0xffffffffu, sum, off);
    const float lse = mx + logf(sum);
    const int orow = (i < N1 + N2) ? (i + N3) : (i - (N1 + N2));
    float4 o = make_float4(v.x - lse, v.y - lse, v.z - lse, v.w - lse);
    ((float4*)out)[orow * 32 + lane] = o;
}

// ---------------- launch ----------------
// Order keeps k_att at ncu launch index 3 (-s 5 -c 1 profiles index 3).
extern "C" void kernel_launch(void* const* d_in, const int* in_sizes, int n_in,
                              void* d_out, int out_size) {
    const float* h   = (const float*)d_in[0];
    const int*   A1  = (const int*)d_in[1];
    const int*   A2  = (const int*)d_in[2];
    const int*   A3  = (const int*)d_in[3];
    const int*   A12 = (const int*)d_in[4];
    const int*   A13 = (const int*)d_in[5];
    const int*   A23 = (const int*)d_in[6];
    const int*   A21 = (const int*)d_in[7];
    const int*   A31 = (const int*)d_in[8];
    const int*   A32 = (const int*)d_in[9];
    const float* Ws  = (const float*)d_in[10];
    const float* ap  = (const float*)d_in[11];

    const int wh_smem = (128 * 68 + 128 * 128) * sizeof(float);   // 100352
    cudaFuncSetAttribute(k_wh,  cudaFuncAttributeMaxDynamicSharedMemorySize, wh_smem);
    cudaFuncSetAttribute(k_att, cudaFuncAttributeMaxDynamicSharedMemorySize, ATT_SMEM);

    k_maskpack<<<NTOT, 256>>>(A1, A2, A3, A12, A13, A23, A21, A31, A32);
    k_scal<<<(HEADS * NTOT + 255) / 256, 256>>>(h, Ws, ap);
    k_wh<<<NTOT / 64, 256, wh_smem>>>(h, Ws);
    k_att<<<dim3(NPAD / MROWS, HEADS), 512, ATT_SMEM>>>();
    k_lsm<<<NTOT / 8, 256>>>((float*)d_out);
}

// round 13
// speedup vs baseline: 1.0734x; 1.0734x over previous
#include <cuda_runtime.h>
#include <cuda_bf16.h>
#include <mma.h>
#include <math.h>
#include <stdint.h>

using namespace nvcuda;

// ---------------- problem constants ----------------
#define N1 3000
#define N2 2500
#define N3 2500
#define NTOT 8000
#define NPAD 8192
#define IN_F 128
#define OUT_F 64
#define HEADS 2
#define MSTR 256               // mask words per row (250 used, 251..255 zero pad)

#define MROWS 128              // rows per k_att CTA
#define TJ 128                 // K per j-tile
#define NTILE_J 63             // ceil(8000/128); tail js zero via padded ffh/mask

#define PSTR 136               // bf16 tile row stride (272B: conflict-free LDSM/STS)
#define CSTR 68                // f32 C tile row stride

// ---------------- device scratch ----------------
__device__ __nv_bfloat16 g_WhT[HEADS * OUT_F * NPAD];  // [head*64+o][n] bf16, 2MB
__device__ float    g_E1[HEADS * NPAD];
__device__ float    g_E2[HEADS * NPAD];
__device__ unsigned g_ffh[HEADS * NPAD];               // bf16x2 {F1,F2} per node
__device__ unsigned g_mask[NPAD * MSTR];               // 8.4MB bitmask (zero pad)
__device__ float    g_x2[NTOT * HEADS * OUT_F];        // 4MB

// ---------------- helpers ----------------
static __device__ __forceinline__ unsigned long long dup2(float x) {
    unsigned long long r;
    asm("mov.b64 %0, {%1, %2};" : "=l"(r) : "f"(x), "f"(x));
    return r;
}
static __device__ __forceinline__ void fma2(unsigned long long &acc,
                                            unsigned long long a, unsigned long long b) {
    asm("fma.rn.f32x2 %0, %1, %2, %0;" : "+l"(acc) : "l"(a), "l"(b));
}
static __device__ __forceinline__ float2 upk(unsigned long long v) {
    float2 f;
    asm("mov.b64 {%0, %1}, %2;" : "=f"(f.x), "=f"(f.y) : "l"(v));
    return f;
}
static __device__ __forceinline__ unsigned cvt_bf16x2(float lo, float hi) {
    unsigned r;
    asm("cvt.rn.satfinite.bf16x2.f32 %0, %1, %2;" : "=r"(r) : "f"(hi), "f"(lo));
    return r;
}

// ---------------- kernel 1: per-node scalars (k_prep fused in) ----------------
__global__ void __launch_bounds__(256) k_scal(const float* __restrict__ h,
                                              const float* __restrict__ Ws,
                                              const float* __restrict__ ap) {
    __shared__ float su[2][2][IN_F];           // [head][which][f]
    const int t = threadIdx.x;

#pragma unroll
    for (int d = 0; d < 2; ++d) {
        const int id = t + 256 * d;            // 0..511
        const int hd = id >> 8, which = (id >> 7) & 1, f = id & 127;
        const float4* w = (const float4*)(Ws + hd * (IN_F * OUT_F) + f * OUT_F);
        const float4* a = (const float4*)(ap + hd * 2 * OUT_F + which * OUT_F);
        float acc = 0.f;
#pragma unroll
        for (int k = 0; k < OUT_F / 4; ++k) {
            float4 wv = w[k], av = a[k];
            acc += wv.x * av.x + wv.y * av.y + wv.z * av.z + wv.w * av.w;
        }
        su[hd][which][f] = acc;
    }
    __syncthreads();

    const int idx = blockIdx.x * 256 + t;
    if (idx >= HEADS * NTOT) return;
    const int hd = idx / NTOT, i = idx % NTOT;
    const int g = hd * NPAD + i;
    const float4* hr = (const float4*)(h + i * IN_F);
    const float4* u1 = (const float4*)(&su[hd][0][0]);
    const float4* u2 = (const float4*)(&su[hd][1][0]);
    float c = 0.f, s = 0.f;
#pragma unroll
    for (int k = 0; k < IN_F / 4; ++k) {
        float4 hv = hr[k], x = u1[k], y = u2[k];
        c += hv.x * x.x + hv.y * x.y + hv.z * x.z + hv.w * x.w;
        s += hv.x * y.x + hv.y * y.y + hv.z * y.z + hv.w * y.w;
    }
    g_E1[g]  = __expf(c);
    g_E2[g]  = __expf(0.2f * c);
    g_ffh[g] = cvt_bf16x2(__expf(s), __expf(0.2f * s));   // {lo=F1, hi=F2}
}

// ---------------- kernel 2: WhT (bf16, transposed) = (h @ Ws)^T ----------------
__global__ void __launch_bounds__(256) k_wh(const float* __restrict__ h,
                                            const float* __restrict__ Ws) {
    extern __shared__ float wsm[];
    float* sh = wsm;                 // [k][n pad 68]
    float* sW = wsm + 128 * 68;      // [k][ho=head*64+o]
    const int tid = threadIdx.x;
    const int n0 = blockIdx.x * 64;

#pragma unroll
    for (int e = 0; e < 16; ++e) {
        const int idx = tid + 256 * e;
        const int hd = idx >> 11, rem = idx & 2047, k = rem >> 4, o4 = rem & 15;
        float4 v = ((const float4*)Ws)[idx];
        *(float4*)&sW[k * 128 + hd * 64 + o4 * 4] = v;
    }
#pragma unroll
    for (int e = 0; e < 8; ++e) {
        const int idx = tid + 256 * e;
        const int n = idx >> 5, k4 = idx & 31;
        float4 v = *(const float4*)(h + (n0 + n) * IN_F + k4 * 4);
        sh[(k4 * 4 + 0) * 68 + n] = v.x;
        sh[(k4 * 4 + 1) * 68 + n] = v.y;
        sh[(k4 * 4 + 2) * 68 + n] = v.z;
        sh[(k4 * 4 + 3) * 68 + n] = v.w;
    }
    __syncthreads();

    const int tx = tid & 15, ty = tid >> 4;     // 8 ho x 4 n per thread
    unsigned long long acc[4][4];
#pragma unroll
    for (int r = 0; r < 4; ++r)
#pragma unroll
        for (int c = 0; c < 4; ++c) acc[r][c] = 0ull;

#pragma unroll 4
    for (int k = 0; k < IN_F; ++k) {
        const float4 hv = *(const float4*)&sh[k * 68 + ty * 4];
        const ulonglong2 wA = *(const ulonglong2*)&sW[k * 128 + tx * 8];
        const ulonglong2 wB = *(const ulonglong2*)&sW[k * 128 + tx * 8 + 4];
        const float hr[4] = {hv.x, hv.y, hv.z, hv.w};
#pragma unroll
        for (int r = 0; r < 4; ++r) {
            const unsigned long long hd2 = dup2(hr[r]);
            fma2(acc[r][0], hd2, wA.x); fma2(acc[r][1], hd2, wA.y);
            fma2(acc[r][2], hd2, wB.x); fma2(acc[r][3], hd2, wB.y);
        }
    }

    float v[4][8];
#pragma unroll
    for (int r = 0; r < 4; ++r)
#pragma unroll
        for (int c = 0; c < 4; ++c) {
            float2 f = upk(acc[r][c]);
            v[r][2 * c] = f.x; v[r][2 * c + 1] = f.y;
        }
#pragma unroll
    for (int hh = 0; hh < 8; ++hh) {
        const int ho = tx * 8 + hh;
        unsigned u0 = cvt_bf16x2(v[0][hh], v[1][hh]);
        unsigned u1 = cvt_bf16x2(v[2][hh], v[3][hh]);
        *(uint2*)((char*)g_WhT + (ho * NPAD + n0 + ty * 4) * 2) = make_uint2(u0, u1);
    }
}

// ---------------- kernel 3: pack block-mask into bitmask (R8 proven, MSTR rows) ----
static __device__ __forceinline__ int4 mask4(
    int i, int j4,
    const int* __restrict__ A1,  const int* __restrict__ A2,  const int* __restrict__ A3,
    const int* __restrict__ A12, const int* __restrict__ A13, const int* __restrict__ A23,
    const int* __restrict__ A21, const int* __restrict__ A31, const int* __restrict__ A32) {
    const int j = j4 * 4;
    if (i < N1) {
        if (j < N1) return *(const int4*)(A1 + i * N1 + j);
        if (j < N1 + N2) return *(const int4*)(A12 + i * N2 + (j - N1));
        return *(const int4*)(A13 + i * N3 + (j - N1 - N2));
    } else if (i < N1 + N2) {
        const int ii = i - N1;
        if (j < N1) return *(const int4*)(A21 + ii * N1 + j);
        if (j < N1 + N2) return *(const int4*)(A2 + ii * N2 + (j - N1));
        return *(const int4*)(A23 + ii * N3 + (j - N1 - N2));
    } else {
        const int ii = i - N1 - N2;
        if (j < N1) return *(const int4*)(A31 + ii * N1 + j);
        if (j < N1 + N2) return *(const int4*)(A32 + ii * N2 + (j - N1));
        return *(const int4*)(A3 + ii * N3 + (j - N1 - N2));
    }
}

__global__ void __launch_bounds__(256) k_maskpack(
    const int* __restrict__ A1,  const int* __restrict__ A2,  const int* __restrict__ A3,
    const int* __restrict__ A12, const int* __restrict__ A13, const int* __restrict__ A23,
    const int* __restrict__ A21, const int* __restrict__ A31, const int* __restrict__ A32) {
    const int row  = blockIdx.x;
    const int t    = threadIdx.x;
    const int lane = t & 31;
    const unsigned gmask = 0xFFu << ((lane >> 3) << 3);
    const int shift = (lane & 7) * 4;

    int4 v[8];
#pragma unroll
    for (int it = 0; it < 8; ++it) {
        const int idx4 = it * 256 + t;           // int4 index within row (0..1999)
        if (idx4 < 2000)
            v[it] = mask4(row, idx4, A1, A2, A3, A12, A13, A23, A21, A31, A32);
    }
#pragma unroll
    for (int it = 0; it < 8; ++it) {
        const int idx4 = it * 256 + t;
        if (idx4 < 2000) {
            const int4 a = v[it];
            unsigned nib = (unsigned)(a.x > 0) | ((unsigned)(a.y > 0) << 1)
                         | ((unsigned)(a.z > 0) << 2) | ((unsigned)(a.w > 0) << 3);
            const unsigned word = __reduce_or_sync(gmask, nib << shift);
            if ((lane & 7) == 0)
                g_mask[row * MSTR + (idx4 >> 3)] = word;
        }
    }
}

// ---------------- kernel 4: fused attention via WMMA bf16, TJ=128 ----------------
// grid (64, 2), 512 threads = 16 warps (8 row-blocks x 2 col-blocks, 16x32 tiles).
// R11 integrated structure: single __syncthreads per tile; double-buffered P/B;
// ALL per-tile inputs register-prefetched one tile ahead. TJ=128 halves the
// barrier count and doubles the MMA run per sync. ff in bf16x2 (one u32 per j).
#define PBUF (MROWS * PSTR)            // 17408 bf16
#define BBUF (OUT_F * PSTR)            // 8704 bf16
#define ATT_SMEM ((2 * PBUF + 2 * BBUF) * 2)   // 104448 B

__global__ void __launch_bounds__(512, 1) k_att() {
    extern __shared__ char dsm[];
    __nv_bfloat16* sP[2] = {(__nv_bfloat16*)dsm, (__nv_bfloat16*)dsm + PBUF};
    __nv_bfloat16* sB[2] = {(__nv_bfloat16*)dsm + 2 * PBUF,
                            (__nv_bfloat16*)dsm + 2 * PBUF + BBUF};
    float* sC = (float*)dsm;           // alias, post-loop (128*68*4 = 34816 B)
    __shared__ float sDen[4][MROWS];

    const int head = blockIdx.y;
    const int i0   = blockIdx.x * MROWS;
    const int hb   = head * NPAD;
    const int tid  = threadIdx.x;
    const int wid  = tid >> 5;

    // p-gen role: row r (0..127), j-quarter q (0..3) -> 32 js
    const int r = tid & 127;
    const int q = tid >> 7;
    const float e1i = g_E1[hb + i0 + r];
    const float e2i = g_E2[hb + i0 + r];
    const unsigned* mrow = g_mask + (i0 + r) * MSTR;
    const int jl0 = q * 32;
    const unsigned* ffh = g_ffh + hb;

    // B-stage role: two 16B granules (64 o-rows x 16 granules = 1024 / 512 thr)
    const int g0 = tid * 2;
    const int bo = g0 >> 4, bg = g0 & 15;
    const char* bsrc = (const char*)g_WhT + ((head * OUT_F + bo) * NPAD) * 2 + bg * 16;
    const int bdst = bo * PSTR + bg * 8;

    // wmma role: 8x2 warp grid, warp tile 16 rows x 32 cols, 8 k-steps
    const int wy = wid & 7, wx = wid >> 3;
    wmma::fragment<wmma::accumulator, 16, 16, 16, float> c0, c1;
    wmma::fill_fragment(c0, 0.f);
    wmma::fill_fragment(c1, 0.f);

    float dsum = 0.f;

    // prefetch tile 0
    uint4 nbg0 = *(const uint4*)bsrc;
    uint4 nbg1 = *(const uint4*)(bsrc + 16);
    uint4 nffr[8];                     // 32 js x bf16x2{F1,F2}
#pragma unroll
    for (int u = 0; u < 8; ++u) nffr[u] = *(const uint4*)(ffh + jl0 + 4 * u);
    unsigned nmw = mrow[q];

#pragma unroll 1
    for (int jt = 0; jt < NTILE_J; ++jt) {
        const int b = jt & 1;

        // ---- STS phase: write tile jt from prefetched regs into buf[b] ----
        *(uint4*)(sB[b] + bdst)     = nbg0;
        *(uint4*)(sB[b] + bdst + 8) = nbg1;
        {
            const unsigned mw = nmw;
            unsigned pk[16];
#pragma unroll
            for (int k2 = 0; k2 < 16; ++k2) {
                const unsigned w0 = ((const unsigned*)nffr)[2 * k2];
                const unsigned w1 = ((const unsigned*)nffr)[2 * k2 + 1];
                const float wa = fmaxf(e1i * __uint_as_float(w0 << 16),
                                       e2i * __uint_as_float(w0 & 0xFFFF0000u));
                const float wb = fmaxf(e1i * __uint_as_float(w1 << 16),
                                       e2i * __uint_as_float(w1 & 0xFFFF0000u));
                const float p0 = ((mw >> (2 * k2))     & 1u) ? wa : 0.f;
                const float p1 = ((mw >> (2 * k2 + 1)) & 1u) ? wb : 0.f;
                dsum += p0 + p1;
                pk[k2] = cvt_bf16x2(p0, p1);
            }
            uint4* d = (uint4*)(sP[b] + r * PSTR + jl0);
            d[0] = make_uint4(pk[0],  pk[1],  pk[2],  pk[3]);
            d[1] = make_uint4(pk[4],  pk[5],  pk[6],  pk[7]);
            d[2] = make_uint4(pk[8],  pk[9],  pk[10], pk[11]);
            d[3] = make_uint4(pk[12], pk[13], pk[14], pk[15]);
        }

        // ---- prefetch tile jt+1 (consumed after next sync + compute) ----
        if (jt + 1 < NTILE_J) {
            const int jb = (jt + 1) * TJ;
            nbg0 = *(const uint4*)(bsrc + jb * 2);
            nbg1 = *(const uint4*)(bsrc + jb * 2 + 16);
#pragma unroll
            for (int u = 0; u < 8; ++u)
                nffr[u] = *(const uint4*)(ffh + jb + jl0 + 4 * u);
            nmw = mrow[(jt + 1) * 4 + q];
        }

        __syncthreads();               // buf[b] complete; prior compute drained

        // ---- compute(jt) from buf[b]: 8 k-steps ----
#pragma unroll
        for (int k = 0; k < 8; ++k) {
            wmma::fragment<wmma::matrix_a, 16, 16, 16, __nv_bfloat16, wmma::row_major> a;
            wmma::fragment<wmma::matrix_b, 16, 16, 16, __nv_bfloat16, wmma::col_major> b0, b1;
            wmma::load_matrix_sync(a, sP[b] + wy * 16 * PSTR + k * 16, PSTR);
            wmma::load_matrix_sync(b0, sB[b] + (wx * 32) * PSTR + k * 16, PSTR);
            wmma::load_matrix_sync(b1, sB[b] + (wx * 32 + 16) * PSTR + k * 16, PSTR);
            wmma::mma_sync(c0, a, b0, c0);
            wmma::mma_sync(c1, a, b1, c1);
        }
    }

    sDen[q][r] = dsum;
    __syncthreads();                   // mainloop fully done; safe to alias

    wmma::store_matrix_sync(sC + wy * 16 * CSTR + wx * 32,      c0, CSTR, wmma::mem_row_major);
    wmma::store_matrix_sync(sC + wy * 16 * CSTR + wx * 32 + 16, c1, CSTR, wmma::mem_row_major);
    __syncthreads();

    // epilogue: normalize, ELU, write (4 cols x 4 groups per thread)
    const int row = tid >> 2, cg = tid & 3;
    if (i0 + row < NTOT) {
        const float den = sDen[0][row] + sDen[1][row] + sDen[2][row] + sDen[3][row];
        const float inv = 1.f / den;
        const float* src = sC + row * CSTR + cg * 16;
        float* op = g_x2 + (i0 + row) * (HEADS * OUT_F) + head * OUT_F + cg * 16;
#pragma unroll
        for (int c4 = 0; c4 < 4; ++c4) {
            float4 v = *(const float4*)(src + c4 * 4);
            float x0 = v.x * inv, x1 = v.y * inv, x2 = v.z * inv, x3 = v.w * inv;
            x0 = (x0 > 0.f) ? x0 : expm1f(x0);
            x1 = (x1 > 0.f) ? x1 : expm1f(x1);
            x2 = (x2 > 0.f) ? x2 : expm1f(x2);
            x3 = (x3 > 0.f) ? x3 : expm1f(x3);
            *(float4*)(op + c4 * 4) = make_float4(x0, x1, x2, x3);
        }
    }
}

// ---------------- kernel 5: log_softmax (128-wide) + permuted row write ----------------
__global__ void __launch_bounds__(256) k_lsm(float* __restrict__ out) {
    const int lane = threadIdx.x & 31;
    const int i = blockIdx.x * 8 + (threadIdx.x >> 5);
    float4 v = ((const float4*)(g_x2 + i * 128))[lane];
    float mx = fmaxf(fmaxf(v.x, v.y), fmaxf(v.z, v.w));
#pragma unroll
    for (int off = 16; off > 0; off >>= 1)
        mx = fmaxf(mx, __shfl_xor_sync(0xffffffffu, mx, off));
    float sum = __expf(v.x - mx) + __expf(v.y - mx) + __expf(v.z - mx) + __expf(v.w - mx);
#pragma unroll
    for (int off = 16; off > 0; off >>= 1)
        sum += __shfl_xor_sync(0xffffffffu, sum, off);
    const float lse = mx + logf(sum);
    const int orow = (i < N1 + N2) ? (i + N3) : (i - (N1 + N2));
    float4 o = make_float4(v.x - lse, v.y - lse, v.z - lse, v.w - lse);
    ((float4*)out)[orow * 32 + lane] = o;
}

// ---------------- launch ----------------
// Order keeps k_att at ncu launch index 3 (-s 5 -c 1 profiles index 3).
extern "C" void kernel_launch(void* const* d_in, const int* in_sizes, int n_in,
                              void* d_out, int out_size) {
    const float* h   = (const float*)d_in[0];
    const int*   A1  = (const int*)d_in[1];
    const int*   A2  = (const int*)d_in[2];
    const int*   A3  = (const int*)d_in[3];
    const int*   A12 = (const int*)d_in[4];
    const int*   A13 = (const int*)d_in[5];
    const int*   A23 = (const int*)d_in[6];
    const int*   A21 = (const int*)d_in[7];
    const int*   A31 = (const int*)d_in[8];
    const int*   A32 = (const int*)d_in[9];
    const float* Ws  = (const float*)d_in[10];
    const float* ap  = (const float*)d_in[11];

    const int wh_smem = (128 * 68 + 128 * 128) * sizeof(float);   // 100352
    cudaFuncSetAttribute(k_wh,  cudaFuncAttributeMaxDynamicSharedMemorySize, wh_smem);
    cudaFuncSetAttribute(k_att, cudaFuncAttributeMaxDynamicSharedMemorySize, ATT_SMEM);

    k_maskpack<<<NTOT, 256>>>(A1, A2, A3, A12, A13, A23, A21, A31, A32);
    k_scal<<<(HEADS * NTOT + 255) / 256, 256>>>(h, Ws, ap);
    k_wh<<<NTOT / 64, 256, wh_smem>>>(h, Ws);
    k_att<<<dim3(NPAD / MROWS, HEADS), 512, ATT_SMEM>>>();
    k_lsm<<<NTOT / 8, 256>>>((float*)d_out);
}

// round 14
// speedup vs baseline: 1.1748x; 1.0944x over previous
#include <cuda_runtime.h>
#include <cuda_bf16.h>
#include <mma.h>
#include <math.h>
#include <stdint.h>

using namespace nvcuda;

// ---------------- problem constants ----------------
#define N1 3000
#define N2 2500
#define N3 2500
#define NTOT 8000
#define NPAD 8192
#define IN_F 128
#define OUT_F 64
#define HEADS 2
#define MSTR 256               // mask words per row (250 used, rest zero pad)

#define MROWS 128              // rows per k_att CTA
#define TJ 128                 // K per j-tile
#define NTILE_J 63             // ceil(8000/128); tail js zero via padded ffh/mask/WhT
#define IBLK 63                // ceil(8000/128) row blocks (drop pad-only CTA)

#define PSTR 136               // bf16 tile row stride (272B: conflict-free)
#define CSTR 68                // f32 C tile row stride

// ---------------- device scratch ----------------
__device__ __nv_bfloat16 g_WhT[HEADS * OUT_F * NPAD];  // [head*64+o][n] bf16, 2MB
__device__ float    g_E1[HEADS * NPAD];
__device__ float    g_E2[HEADS * NPAD];
__device__ unsigned g_ffh[HEADS * NPAD];               // bf16x2 {F1,F2} per node
__device__ unsigned g_mask[NPAD * MSTR];               // 8.4MB bitmask (zero pad)
__device__ float    g_x2[NTOT * HEADS * OUT_F];        // 4MB

// ---------------- helpers ----------------
static __device__ __forceinline__ unsigned long long dup2(float x) {
    unsigned long long r;
    asm("mov.b64 %0, {%1, %2};" : "=l"(r) : "f"(x), "f"(x));
    return r;
}
static __device__ __forceinline__ void fma2(unsigned long long &acc,
                                            unsigned long long a, unsigned long long b) {
    asm("fma.rn.f32x2 %0, %1, %2, %0;" : "+l"(acc) : "l"(a), "l"(b));
}
static __device__ __forceinline__ float2 upk(unsigned long long v) {
    float2 f;
    asm("mov.b64 {%0, %1}, %2;" : "=f"(f.x), "=f"(f.y) : "l"(v));
    return f;
}
static __device__ __forceinline__ unsigned cvt_bf16x2(float lo, float hi) {
    unsigned r;
    asm("cvt.rn.satfinite.bf16x2.f32 %0, %1, %2;" : "=r"(r) : "f"(hi), "f"(lo));
    return r;
}

// ---------------- kernel 1: per-node scalars (k_prep fused in) ----------------
__global__ void __launch_bounds__(256) k_scal(const float* __restrict__ h,
                                              const float* __restrict__ Ws,
                                              const float* __restrict__ ap) {
    __shared__ float su[2][2][IN_F];           // [head][which][f]
    const int t = threadIdx.x;

#pragma unroll
    for (int d = 0; d < 2; ++d) {
        const int id = t + 256 * d;            // 0..511
        const int hd = id >> 8, which = (id >> 7) & 1, f = id & 127;
        const float4* w = (const float4*)(Ws + hd * (IN_F * OUT_F) + f * OUT_F);
        const float4* a = (const float4*)(ap + hd * 2 * OUT_F + which * OUT_F);
        float acc = 0.f;
#pragma unroll
        for (int k = 0; k < OUT_F / 4; ++k) {
            float4 wv = w[k], av = a[k];
            acc += wv.x * av.x + wv.y * av.y + wv.z * av.z + wv.w * av.w;
        }
        su[hd][which][f] = acc;
    }
    __syncthreads();

    const int idx = blockIdx.x * 256 + t;
    if (idx >= HEADS * NTOT) return;
    const int hd = idx / NTOT, i = idx % NTOT;
    const int g = hd * NPAD + i;
    const float4* hr = (const float4*)(h + i * IN_F);
    const float4* u1 = (const float4*)(&su[hd][0][0]);
    const float4* u2 = (const float4*)(&su[hd][1][0]);
    float c = 0.f, s = 0.f;
#pragma unroll
    for (int k = 0; k < IN_F / 4; ++k) {
        float4 hv = hr[k], x = u1[k], y = u2[k];
        c += hv.x * x.x + hv.y * x.y + hv.z * x.z + hv.w * x.w;
        s += hv.x * y.x + hv.y * y.y + hv.z * y.z + hv.w * y.w;
    }
    g_E1[g]  = __expf(c);
    g_E2[g]  = __expf(0.2f * c);
    g_ffh[g] = cvt_bf16x2(__expf(s), __expf(0.2f * s));   // {lo=F1, hi=F2}
}

// ---------------- kernel 2: WhT (bf16, transposed) = (h @ Ws)^T ----------------
__global__ void __launch_bounds__(256) k_wh(const float* __restrict__ h,
                                            const float* __restrict__ Ws) {
    extern __shared__ float wsm[];
    float* sh = wsm;                 // [k][n pad 68]
    float* sW = wsm + 128 * 68;      // [k][ho=head*64+o]
    const int tid = threadIdx.x;
    const int n0 = blockIdx.x * 64;

#pragma unroll
    for (int e = 0; e < 16; ++e) {
        const int idx = tid + 256 * e;
        const int hd = idx >> 11, rem = idx & 2047, k = rem >> 4, o4 = rem & 15;
        float4 v = ((const float4*)Ws)[idx];
        *(float4*)&sW[k * 128 + hd * 64 + o4 * 4] = v;
    }
#pragma unroll
    for (int e = 0; e < 8; ++e) {
        const int idx = tid + 256 * e;
        const int n = idx >> 5, k4 = idx & 31;
        float4 v = *(const float4*)(h + (n0 + n) * IN_F + k4 * 4);
        sh[(k4 * 4 + 0) * 68 + n] = v.x;
        sh[(k4 * 4 + 1) * 68 + n] = v.y;
        sh[(k4 * 4 + 2) * 68 + n] = v.z;
        sh[(k4 * 4 + 3) * 68 + n] = v.w;
    }
    __syncthreads();

    const int tx = tid & 15, ty = tid >> 4;     // 8 ho x 4 n per thread
    unsigned long long acc[4][4];
#pragma unroll
    for (int r = 0; r < 4; ++r)
#pragma unroll
        for (int c = 0; c < 4; ++c) acc[r][c] = 0ull;

#pragma unroll 4
    for (int k = 0; k < IN_F; ++k) {
        const float4 hv = *(const float4*)&sh[k * 68 + ty * 4];
        const ulonglong2 wA = *(const ulonglong2*)&sW[k * 128 + tx * 8];
        const ulonglong2 wB = *(const ulonglong2*)&sW[k * 128 + tx * 8 + 4];
        const float hr[4] = {hv.x, hv.y, hv.z, hv.w};
#pragma unroll
        for (int r = 0; r < 4; ++r) {
            const unsigned long long hd2 = dup2(hr[r]);
            fma2(acc[r][0], hd2, wA.x); fma2(acc[r][1], hd2, wA.y);
            fma2(acc[r][2], hd2, wB.x); fma2(acc[r][3], hd2, wB.y);
        }
    }

    float v[4][8];
#pragma unroll
    for (int r = 0; r < 4; ++r)
#pragma unroll
        for (int c = 0; c < 4; ++c) {
            float2 f = upk(acc[r][c]);
            v[r][2 * c] = f.x; v[r][2 * c + 1] = f.y;
        }
#pragma unroll
    for (int hh = 0; hh < 8; ++hh) {
        const int ho = tx * 8 + hh;
        unsigned u0 = cvt_bf16x2(v[0][hh], v[1][hh]);
        unsigned u1 = cvt_bf16x2(v[2][hh], v[3][hh]);
        *(uint2*)((char*)g_WhT + (ho * NPAD + n0 + ty * 4) * 2) = make_uint2(u0, u1);
    }
}

// ---------------- kernel 3: pack block-mask into bitmask (R8 proven, MSTR rows) ----
static __device__ __forceinline__ int4 mask4(
    int i, int j4,
    const int* __restrict__ A1,  const int* __restrict__ A2,  const int* __restrict__ A3,
    const int* __restrict__ A12, const int* __restrict__ A13, const int* __restrict__ A23,
    const int* __restrict__ A21, const int* __restrict__ A31, const int* __restrict__ A32) {
    const int j = j4 * 4;
    if (i < N1) {
        if (j < N1) return *(const int4*)(A1 + i * N1 + j);
        if (j < N1 + N2) return *(const int4*)(A12 + i * N2 + (j - N1));
        return *(const int4*)(A13 + i * N3 + (j - N1 - N2));
    } else if (i < N1 + N2) {
        const int ii = i - N1;
        if (j < N1) return *(const int4*)(A21 + ii * N1 + j);
        if (j < N1 + N2) return *(const int4*)(A2 + ii * N2 + (j - N1));
        return *(const int4*)(A23 + ii * N3 + (j - N1 - N2));
    } else {
        const int ii = i - N1 - N2;
        if (j < N1) return *(const int4*)(A31 + ii * N1 + j);
        if (j < N1 + N2) return *(const int4*)(A32 + ii * N2 + (j - N1));
        return *(const int4*)(A3 + ii * N3 + (j - N1 - N2));
    }
}

__global__ void __launch_bounds__(256) k_maskpack(
    const int* __restrict__ A1,  const int* __restrict__ A2,  const int* __restrict__ A3,
    const int* __restrict__ A12, const int* __restrict__ A13, const int* __restrict__ A23,
    const int* __restrict__ A21, const int* __restrict__ A31, const int* __restrict__ A32) {
    const int row  = blockIdx.x;
    const int t    = threadIdx.x;
    const int lane = t & 31;
    const unsigned gmask = 0xFFu << ((lane >> 3) << 3);
    const int shift = (lane & 7) * 4;

    int4 v[8];
#pragma unroll
    for (int it = 0; it < 8; ++it) {
        const int idx4 = it * 256 + t;           // int4 index within row (0..1999)
        if (idx4 < 2000)
            v[it] = mask4(row, idx4, A1, A2, A3, A12, A13, A23, A21, A31, A32);
    }
#pragma unroll
    for (int it = 0; it < 8; ++it) {
        const int idx4 = it * 256 + t;
        if (idx4 < 2000) {
            const int4 a = v[it];
            unsigned nib = (unsigned)(a.x > 0) | ((unsigned)(a.y > 0) << 1)
                         | ((unsigned)(a.z > 0) << 2) | ((unsigned)(a.w > 0) << 3);
            const unsigned word = __reduce_or_sync(gmask, nib << shift);
            if ((lane & 7) == 0)
                g_mask[row * MSTR + (idx4 >> 3)] = word;
        }
    }
}

// ---------------- kernel 4: fused attention, 32x32 warp tiles + k-split ----------------
// grid (63, 2), 512 threads = 16 warps: kg = wid>>3 (k-group, 4 of 8 k-steps),
// (wy,wx) = 4x2 grid of 32x32 warp tiles (4 accum frags). B-frag sharing 8->4,
// A-frag duplication removed: LDSM wavefronts cut ~33%. Partial C from the two
// k-groups merged in the epilogue (exact fp32 add). ffh via tiny smem staging
// (sFF, double-buffered, 4-reg prefetch) instead of the 32-reg prefetch.
// Single __syncthreads per tile; B/mask register prefetch as proven.
#define PB_BYTES (MROWS * PSTR * 2)    // 34816
#define BB_BYTES (OUT_F * PSTR * 2)    // 17408
#define FF_BYTES (TJ * 4)              // 512
#define ATT_SMEM (2 * PB_BYTES + 2 * BB_BYTES + 2 * FF_BYTES)   // 105472

__global__ void __launch_bounds__(512, 1) k_att() {
    extern __shared__ char dsm[];
    __nv_bfloat16* sP[2] = {(__nv_bfloat16*)dsm,
                            (__nv_bfloat16*)(dsm + PB_BYTES)};
    __nv_bfloat16* sB[2] = {(__nv_bfloat16*)(dsm + 2 * PB_BYTES),
                            (__nv_bfloat16*)(dsm + 2 * PB_BYTES + BB_BYTES)};
    unsigned* sFF[2] = {(unsigned*)(dsm + 2 * PB_BYTES + 2 * BB_BYTES),
                        (unsigned*)(dsm + 2 * PB_BYTES + 2 * BB_BYTES + FF_BYTES)};
    float* sCa = (float*)dsm;                          // alias, post-loop
    float* sCb = sCa + MROWS * CSTR;                   // 2*34816 <= 105472
    __shared__ float sDen[4][MROWS];

    const int head = blockIdx.y;
    const int i0   = blockIdx.x * MROWS;
    const int hb   = head * NPAD;
    const int tid  = threadIdx.x;
    const int wid  = tid >> 5;

    // p-gen role: row r (0..127), j-quarter q (0..3) -> 32 js
    const int r = tid & 127;
    const int q = tid >> 7;
    const float e1i = g_E1[hb + i0 + r];
    const float e2i = g_E2[hb + i0 + r];
    const unsigned* mrow = g_mask + (i0 + r) * MSTR;
    const int jl0 = q * 32;
    const unsigned* ffh = g_ffh + hb;

    // B-stage role: two 16B granules (64 o-rows x 16 granules = 1024 / 512 thr)
    const int g0 = tid * 2;
    const int bo = g0 >> 4, bg = g0 & 15;
    const char* bsrc = (const char*)g_WhT + ((head * OUT_F + bo) * NPAD) * 2 + bg * 16;
    const int bdst = bo * PSTR + bg * 8;

    // wmma role: kg-split, 4x2 grid of 32x32 tiles
    const int kg = wid >> 3;
    const int wy = wid & 3, wx = (wid >> 2) & 1;
    wmma::fragment<wmma::accumulator, 16, 16, 16, float> c00, c01, c10, c11;
    wmma::fill_fragment(c00, 0.f);
    wmma::fill_fragment(c01, 0.f);
    wmma::fill_fragment(c10, 0.f);
    wmma::fill_fragment(c11, 0.f);

    float dsum = 0.f;

    // prologue: prefetch tile 0 (B, mask) + stage sFF[0], prefetch ffh tile 1
    uint4 nbg0 = *(const uint4*)bsrc;
    uint4 nbg1 = *(const uint4*)(bsrc + 16);
    unsigned nmw = mrow[q];
    uint4 nffu;
    if (tid < 32) {
        *(uint4*)(sFF[0] + tid * 4) = *(const uint4*)(ffh + tid * 4);
        nffu = *(const uint4*)(ffh + TJ + tid * 4);
    }
    __syncthreads();                   // sFF[0] visible

#pragma unroll 1
    for (int jt = 0; jt < NTILE_J; ++jt) {
        const int b = jt & 1;

        // ---- STS phase: write tile jt from prefetched regs into buf[b] ----
        *(uint4*)(sB[b] + bdst)     = nbg0;
        *(uint4*)(sB[b] + bdst + 8) = nbg1;
        if (jt + 1 < NTILE_J && tid < 32)
            *(uint4*)(sFF[b ^ 1] + tid * 4) = nffu;   // ffh for tile jt+1
        {
            const unsigned mw = nmw;
            const unsigned* ffb = sFF[b] + jl0;
            unsigned pk[16];
#pragma unroll
            for (int k2 = 0; k2 < 16; ++k2) {
                const uint2 ww = *(const uint2*)(ffb + 2 * k2);
                const unsigned w0 = ww.x, w1 = ww.y;
                const float wa = fmaxf(e1i * __uint_as_float(w0 << 16),
                                       e2i * __uint_as_float(w0 & 0xFFFF0000u));
                const float wb = fmaxf(e1i * __uint_as_float(w1 << 16),
                                       e2i * __uint_as_float(w1 & 0xFFFF0000u));
                const float p0 = ((mw >> (2 * k2))     & 1u) ? wa : 0.f;
                const float p1 = ((mw >> (2 * k2 + 1)) & 1u) ? wb : 0.f;
                dsum += p0 + p1;
                pk[k2] = cvt_bf16x2(p0, p1);
            }
            uint4* d = (uint4*)(sP[b] + r * PSTR + jl0);
            d[0] = make_uint4(pk[0],  pk[1],  pk[2],  pk[3]);
            d[1] = make_uint4(pk[4],  pk[5],  pk[6],  pk[7]);
            d[2] = make_uint4(pk[8],  pk[9],  pk[10], pk[11]);
            d[3] = make_uint4(pk[12], pk[13], pk[14], pk[15]);
        }

        // ---- prefetch tile jt+1 (B, mask) and tile jt+2 (ffh) ----
        if (jt + 1 < NTILE_J) {
            const int jb = (jt + 1) * TJ;
            nbg0 = *(const uint4*)(bsrc + jb * 2);
            nbg1 = *(const uint4*)(bsrc + jb * 2 + 16);
            nmw = mrow[(jt + 1) * 4 + q];
            if (jt + 2 < NTILE_J && tid < 32)
                nffu = *(const uint4*)(ffh + (jt + 2) * TJ + tid * 4);
        }

        __syncthreads();               // buf[b] complete; prior compute drained

        // ---- compute(jt) from buf[b]: this warp's 4 k-steps ----
#pragma unroll
        for (int ks = 0; ks < 4; ++ks) {
            const int k = kg * 4 + ks;
            wmma::fragment<wmma::matrix_a, 16, 16, 16, __nv_bfloat16, wmma::row_major> aL, aH;
            wmma::fragment<wmma::matrix_b, 16, 16, 16, __nv_bfloat16, wmma::col_major> b0, b1;
            wmma::load_matrix_sync(aL, sP[b] + (wy * 32) * PSTR + k * 16, PSTR);
            wmma::load_matrix_sync(aH, sP[b] + (wy * 32 + 16) * PSTR + k * 16, PSTR);
            wmma::load_matrix_sync(b0, sB[b] + (wx * 32) * PSTR + k * 16, PSTR);
            wmma::load_matrix_sync(b1, sB[b] + (wx * 32 + 16) * PSTR + k * 16, PSTR);
            wmma::mma_sync(c00, aL, b0, c00);
            wmma::mma_sync(c01, aL, b1, c01);
            wmma::mma_sync(c10, aH, b0, c10);
            wmma::mma_sync(c11, aH, b1, c11);
        }
    }

    sDen[q][r] = dsum;
    __syncthreads();                   // mainloop fully done; safe to alias

    // store partial C per k-group, then merge in the final epilogue
    {
        float* dst = (kg == 0) ? sCa : sCb;
        const int rb = wy * 32, cb = wx * 32;
        wmma::store_matrix_sync(dst + rb * CSTR + cb,               c00, CSTR, wmma::mem_row_major);
        wmma::store_matrix_sync(dst + rb * CSTR + cb + 16,          c01, CSTR, wmma::mem_row_major);
        wmma::store_matrix_sync(dst + (rb + 16) * CSTR + cb,        c10, CSTR, wmma::mem_row_major);
        wmma::store_matrix_sync(dst + (rb + 16) * CSTR + cb + 16,   c11, CSTR, wmma::mem_row_major);
    }
    __syncthreads();

    // epilogue: merge k-groups, normalize, ELU, write
    const int row = tid >> 2, cg = tid & 3;
    if (i0 + row < NTOT) {
        const float den = sDen[0][row] + sDen[1][row] + sDen[2][row] + sDen[3][row];
        const float inv = 1.f / den;
        const float* sa = sCa + row * CSTR + cg * 16;
        const float* sb = sCb + row * CSTR + cg * 16;
        float* op = g_x2 + (i0 + row) * (HEADS * OUT_F) + head * OUT_F + cg * 16;
#pragma unroll
        for (int c4 = 0; c4 < 4; ++c4) {
            float4 va = *(const float4*)(sa + c4 * 4);
            float4 vb = *(const float4*)(sb + c4 * 4);
            float x0 = (va.x + vb.x) * inv, x1 = (va.y + vb.y) * inv;
            float x2 = (va.z + vb.z) * inv, x3 = (va.w + vb.w) * inv;
            x0 = (x0 > 0.f) ? x0 : expm1f(x0);
            x1 = (x1 > 0.f) ? x1 : expm1f(x1);
            x2 = (x2 > 0.f) ? x2 : expm1f(x2);
            x3 = (x3 > 0.f) ? x3 : expm1f(x3);
            *(float4*)(op + c4 * 4) = make_float4(x0, x1, x2, x3);
        }
    }
}

// ---------------- kernel 5: log_softmax (128-wide) + permuted row write ----------------
__global__ void __launch_bounds__(256) k_lsm(float* __restrict__ out) {
    const int lane = threadIdx.x & 31;
    const int i = blockIdx.x * 8 + (threadIdx.x >> 5);
    float4 v = ((const float4*)(g_x2 + i * 128))[lane];
    float mx = fmaxf(fmaxf(v.x, v.y), fmaxf(v.z, v.w));
#pragma unroll
    for (int off = 16; off > 0; off >>= 1)
        mx = fmaxf(mx, __shfl_xor_sync(0xffffffffu, mx, off));
    float sum = __expf(v.x - mx) + __expf(v.y - mx) + __expf(v.z - mx) + __expf(v.w - mx);
#pragma unroll
    for (int off = 16; off > 0; off >>= 1)
        sum += __shfl_xor_sync(0xffffffffu, sum, off);
    const float lse = mx + logf(sum);
    const int orow = (i < N1 + N2) ? (i + N3) : (i - (N1 + N2));
    float4 o = make_float4(v.x - lse, v.y - lse, v.z - lse, v.w - lse);
    ((float4*)out)[orow * 32 + lane] = o;
}

// ---------------- launch ----------------
// Order keeps k_att at ncu launch index 3 (-s 5 -c 1 profiles index 3).
extern "C" void kernel_launch(void* const* d_in, const int* in_sizes, int n_in,
                              void* d_out, int out_size) {
    const float* h   = (const float*)d_in[0];
    const int*   A1  = (const int*)d_in[1];
    const int*   A2  = (const int*)d_in[2];
    const int*   A3  = (const int*)d_in[3];
    const int*   A12 = (const int*)d_in[4];
    const int*   A13 = (const int*)d_in[5];
    const int*   A23 = (const int*)d_in[6];
    const int*   A21 = (const int*)d_in[7];
    const int*   A31 = (const int*)d_in[8];
    const int*   A32 = (const int*)d_in[9];
    const float* Ws  = (const float*)d_in[10];
    const float* ap  = (const float*)d_in[11];

    const int wh_smem = (128 * 68 + 128 * 128) * sizeof(float);   // 100352
    cudaFuncSetAttribute(k_wh,  cudaFuncAttributeMaxDynamicSharedMemorySize, wh_smem);
    cudaFuncSetAttribute(k_att, cudaFuncAttributeMaxDynamicSharedMemorySize, ATT_SMEM);

    k_maskpack<<<NTOT, 256>>>(A1, A2, A3, A12, A13, A23, A21, A31, A32);
    k_scal<<<(HEADS * NTOT + 255) / 256, 256>>>(h, Ws, ap);
    k_wh<<<NTOT / 64, 256, wh_smem>>>(h, Ws);
    k_att<<<dim3(IBLK, HEADS), 512, ATT_SMEM>>>();
    k_lsm<<<NTOT / 8, 256>>>((float*)d_out);
}

// round 15
// speedup vs baseline: 1.1824x; 1.0065x over previous
#include <cuda_runtime.h>
#include <cuda_bf16.h>
#include <mma.h>
#include <math.h>
#include <stdint.h>

using namespace nvcuda;

// ---------------- problem constants ----------------
#define N1 3000
#define N2 2500
#define N3 2500
#define NTOT 8000
#define NPAD 8192
#define IN_F 128
#define OUT_F 64
#define HEADS 2
#define MSTR 256               // mask words per row (250 used, rest zero pad)

#define MROWS 128              // rows per k_att CTA
#define TJ 128                 // K per j-tile
#define NTILE_J 63             // ceil(8000/128); tail js zero via padded ffh/mask/WhT
#define IBLK 63                // ceil(8000/128) row blocks

#define PSTR 136               // bf16 tile row stride (272B: conflict-free)
#define CSTR 68                // f32 C tile row stride

// ---------------- device scratch ----------------
__device__ __nv_bfloat16 g_WhT[HEADS * OUT_F * NPAD];  // [head*64+o][n] bf16, 2MB
__device__ float    g_E1[HEADS * NPAD];
__device__ float    g_E2[HEADS * NPAD];
__device__ unsigned g_ffh[HEADS * NPAD];               // bf16x2 {F1,F2} per node
__device__ unsigned g_mask[NPAD * MSTR];               // 8.4MB bitmask (zero pad)
__device__ float    g_x2[NTOT * HEADS * OUT_F];        // 4MB

// ---------------- helpers ----------------
static __device__ __forceinline__ unsigned long long dup2(float x) {
    unsigned long long r;
    asm("mov.b64 %0, {%1, %2};" : "=l"(r) : "f"(x), "f"(x));
    return r;
}
static __device__ __forceinline__ void fma2(unsigned long long &acc,
                                            unsigned long long a, unsigned long long b) {
    asm("fma.rn.f32x2 %0, %1, %2, %0;" : "+l"(acc) : "l"(a), "l"(b));
}
static __device__ __forceinline__ float2 upk(unsigned long long v) {
    float2 f;
    asm("mov.b64 {%0, %1}, %2;" : "=f"(f.x), "=f"(f.y) : "l"(v));
    return f;
}
static __device__ __forceinline__ unsigned cvt_bf16x2(float lo, float hi) {
    unsigned r;
    asm("cvt.rn.satfinite.bf16x2.f32 %0, %1, %2;" : "=r"(r) : "f"(hi), "f"(lo));
    return r;
}
static __device__ __forceinline__ unsigned mul_bf16x2(unsigned a, unsigned b) {
    unsigned r;
    asm("mul.bf16x2 %0, %1, %2;" : "=r"(r) : "r"(a), "r"(b));
    return r;
}
static __device__ __forceinline__ unsigned max_bf16x2(unsigned a, unsigned b) {
    unsigned r;
    asm("max.bf16x2 %0, %1, %2;" : "=r"(r) : "r"(a), "r"(b));
    return r;
}

// ---------------- kernel 1: per-node scalars (k_prep fused in) ----------------
__global__ void __launch_bounds__(256) k_scal(const float* __restrict__ h,
                                              const float* __restrict__ Ws,
                                              const float* __restrict__ ap) {
    __shared__ float su[2][2][IN_F];           // [head][which][f]
    const int t = threadIdx.x;

#pragma unroll
    for (int d = 0; d < 2; ++d) {
        const int id = t + 256 * d;            // 0..511
        const int hd = id >> 8, which = (id >> 7) & 1, f = id & 127;
        const float4* w = (const float4*)(Ws + hd * (IN_F * OUT_F) + f * OUT_F);
        const float4* a = (const float4*)(ap + hd * 2 * OUT_F + which * OUT_F);
        float acc = 0.f;
#pragma unroll
        for (int k = 0; k < OUT_F / 4; ++k) {
            float4 wv = w[k], av = a[k];
            acc += wv.x * av.x + wv.y * av.y + wv.z * av.z + wv.w * av.w;
        }
        su[hd][which][f] = acc;
    }
    __syncthreads();

    const int idx = blockIdx.x * 256 + t;
    if (idx >= HEADS * NTOT) return;
    const int hd = idx / NTOT, i = idx % NTOT;
    const int g = hd * NPAD + i;
    const float4* hr = (const float4*)(h + i * IN_F);
    const float4* u1 = (const float4*)(&su[hd][0][0]);
    const float4* u2 = (const float4*)(&su[hd][1][0]);
    float c = 0.f, s = 0.f;
#pragma unroll
    for (int k = 0; k < IN_F / 4; ++k) {
        float4 hv = hr[k], x = u1[k], y = u2[k];
        c += hv.x * x.x + hv.y * x.y + hv.z * x.z + hv.w * x.w;
        s += hv.x * y.x + hv.y * y.y + hv.z * y.z + hv.w * y.w;
    }
    g_E1[g]  = __expf(c);
    g_E2[g]  = __expf(0.2f * c);
    g_ffh[g] = cvt_bf16x2(__expf(s), __expf(0.2f * s));   // {lo=F1, hi=F2}
}

// ---------------- kernel 2: WhT (bf16, transposed) = (h @ Ws)^T ----------------
__global__ void __launch_bounds__(256) k_wh(const float* __restrict__ h,
                                            const float* __restrict__ Ws) {
    extern __shared__ float wsm[];
    float* sh = wsm;                 // [k][n pad 68]
    float* sW = wsm + 128 * 68;      // [k][ho=head*64+o]
    const int tid = threadIdx.x;
    const int n0 = blockIdx.x * 64;

#pragma unroll
    for (int e = 0; e < 16; ++e) {
        const int idx = tid + 256 * e;
        const int hd = idx >> 11, rem = idx & 2047, k = rem >> 4, o4 = rem & 15;
        float4 v = ((const float4*)Ws)[idx];
        *(float4*)&sW[k * 128 + hd * 64 + o4 * 4] = v;
    }
#pragma unroll
    for (int e = 0; e < 8; ++e) {
        const int idx = tid + 256 * e;
        const int n = idx >> 5, k4 = idx & 31;
        float4 v = *(const float4*)(h + (n0 + n) * IN_F + k4 * 4);
        sh[(k4 * 4 + 0) * 68 + n] = v.x;
        sh[(k4 * 4 + 1) * 68 + n] = v.y;
        sh[(k4 * 4 + 2) * 68 + n] = v.z;
        sh[(k4 * 4 + 3) * 68 + n] = v.w;
    }
    __syncthreads();

    const int tx = tid & 15, ty = tid >> 4;     // 8 ho x 4 n per thread
    unsigned long long acc[4][4];
#pragma unroll
    for (int r = 0; r < 4; ++r)
#pragma unroll
        for (int c = 0; c < 4; ++c) acc[r][c] = 0ull;

#pragma unroll 4
    for (int k = 0; k < IN_F; ++k) {
        const float4 hv = *(const float4*)&sh[k * 68 + ty * 4];
        const ulonglong2 wA = *(const ulonglong2*)&sW[k * 128 + tx * 8];
        const ulonglong2 wB = *(const ulonglong2*)&sW[k * 128 + tx * 8 + 4];
        const float hr[4] = {hv.x, hv.y, hv.z, hv.w};
#pragma unroll
        for (int r = 0; r < 4; ++r) {
            const unsigned long long hd2 = dup2(hr[r]);
            fma2(acc[r][0], hd2, wA.x); fma2(acc[r][1], hd2, wA.y);
            fma2(acc[r][2], hd2, wB.x); fma2(acc[r][3], hd2, wB.y);
        }
    }

    float v[4][8];
#pragma unroll
    for (int r = 0; r < 4; ++r)
#pragma unroll
        for (int c = 0; c < 4; ++c) {
            float2 f = upk(acc[r][c]);
            v[r][2 * c] = f.x; v[r][2 * c + 1] = f.y;
        }
#pragma unroll
    for (int hh = 0; hh < 8; ++hh) {
        const int ho = tx * 8 + hh;
        unsigned u0 = cvt_bf16x2(v[0][hh], v[1][hh]);
        unsigned u1 = cvt_bf16x2(v[2][hh], v[3][hh]);
        *(uint2*)((char*)g_WhT + (ho * NPAD + n0 + ty * 4) * 2) = make_uint2(u0, u1);
    }
}

// ---------------- kernel 3: pack block-mask into bitmask (R8 proven, MSTR rows) ----
static __device__ __forceinline__ int4 mask4(
    int i, int j4,
    const int* __restrict__ A1,  const int* __restrict__ A2,  const int* __restrict__ A3,
    const int* __restrict__ A12, const int* __restrict__ A13, const int* __restrict__ A23,
    const int* __restrict__ A21, const int* __restrict__ A31, const int* __restrict__ A32) {
    const int j = j4 * 4;
    if (i < N1) {
        if (j < N1) return *(const int4*)(A1 + i * N1 + j);
        if (j < N1 + N2) return *(const int4*)(A12 + i * N2 + (j - N1));
        return *(const int4*)(A13 + i * N3 + (j - N1 - N2));
    } else if (i < N1 + N2) {
        const int ii = i - N1;
        if (j < N1) return *(const int4*)(A21 + ii * N1 + j);
        if (j < N1 + N2) return *(const int4*)(A2 + ii * N2 + (j - N1));
        return *(const int4*)(A23 + ii * N3 + (j - N1 - N2));
    } else {
        const int ii = i - N1 - N2;
        if (j < N1) return *(const int4*)(A31 + ii * N1 + j);
        if (j < N1 + N2) return *(const int4*)(A32 + ii * N2 + (j - N1));
        return *(const int4*)(A3 + ii * N3 + (j - N1 - N2));
    }
}

__global__ void __launch_bounds__(256) k_maskpack(
    const int* __restrict__ A1,  const int* __restrict__ A2,  const int* __restrict__ A3,
    const int* __restrict__ A12, const int* __restrict__ A13, const int* __restrict__ A23,
    const int* __restrict__ A21, const int* __restrict__ A31, const int* __restrict__ A32) {
    const int row  = blockIdx.x;
    const int t    = threadIdx.x;
    const int lane = t & 31;
    const unsigned gmask = 0xFFu << ((lane >> 3) << 3);
    const int shift = (lane & 7) * 4;

    int4 v[8];
#pragma unroll
    for (int it = 0; it < 8; ++it) {
        const int idx4 = it * 256 + t;           // int4 index within row (0..1999)
        if (idx4 < 2000)
            v[it] = mask4(row, idx4, A1, A2, A3, A12, A13, A23, A21, A31, A32);
    }
#pragma unroll
    for (int it = 0; it < 8; ++it) {
        const int idx4 = it * 256 + t;
        if (idx4 < 2000) {
            const int4 a = v[it];
            unsigned nib = (unsigned)(a.x > 0) | ((unsigned)(a.y > 0) << 1)
                         | ((unsigned)(a.z > 0) << 2) | ((unsigned)(a.w > 0) << 3);
            const unsigned word = __reduce_or_sync(gmask, nib << shift);
            if ((lane & 7) == 0)
                g_mask[row * MSTR + (idx4 >> 3)] = word;
        }
    }
}

// ---------------- kernel 4: fused attention, 32x32 warp tiles + k-split ----------------
// grid (63, 2), 512 threads = 16 warps: kg = wid>>3 (k-group, 4 of 8 k-steps),
// (wy,wx) = 4x2 grid of 32x32 warp tiles. Packed bf16x2 p-gen: pre-masked
// mul.bf16x2 with {e1,e2}, byte_perm transpose, max.bf16x2 -> {p0,p1} directly
// in store format (exp monotone: lrelu-exp select == max; all factors > 0).
// dsum sums the SAME bf16 p the MMA consumes. Single __syncthreads per tile.
#define PB_BYTES (MROWS * PSTR * 2)    // 34816
#define BB_BYTES (OUT_F * PSTR * 2)    // 17408
#define FF_BYTES (TJ * 4)              // 512
#define ATT_SMEM (2 * PB_BYTES + 2 * BB_BYTES + 2 * FF_BYTES)   // 105472

__global__ void __launch_bounds__(512, 1) k_att() {
    extern __shared__ char dsm[];
    __nv_bfloat16* sP[2] = {(__nv_bfloat16*)dsm,
                            (__nv_bfloat16*)(dsm + PB_BYTES)};
    __nv_bfloat16* sB[2] = {(__nv_bfloat16*)(dsm + 2 * PB_BYTES),
                            (__nv_bfloat16*)(dsm + 2 * PB_BYTES + BB_BYTES)};
    unsigned* sFF[2] = {(unsigned*)(dsm + 2 * PB_BYTES + 2 * BB_BYTES),
                        (unsigned*)(dsm + 2 * PB_BYTES + 2 * BB_BYTES + FF_BYTES)};
    float* sCa = (float*)dsm;                          // alias, post-loop
    float* sCb = sCa + MROWS * CSTR;
    __shared__ float sDen[4][MROWS];

    const int head = blockIdx.y;
    const int i0   = blockIdx.x * MROWS;
    const int hb   = head * NPAD;
    const int tid  = threadIdx.x;
    const int wid  = tid >> 5;

    // p-gen role: row r (0..127), j-quarter q (0..3) -> 32 js
    const int r = tid & 127;
    const int q = tid >> 7;
    const unsigned epk = cvt_bf16x2(g_E1[hb + i0 + r], g_E2[hb + i0 + r]); // {e1,e2}
    const unsigned* mrow = g_mask + (i0 + r) * MSTR;
    const int jl0 = q * 32;
    const unsigned* ffh = g_ffh + hb;

    // B-stage role: two 16B granules (64 o-rows x 16 granules = 1024 / 512 thr)
    const int g0 = tid * 2;
    const int bo = g0 >> 4, bg = g0 & 15;
    const char* bsrc = (const char*)g_WhT + ((head * OUT_F + bo) * NPAD) * 2 + bg * 16;
    const int bdst = bo * PSTR + bg * 8;

    // wmma role: kg-split, 4x2 grid of 32x32 tiles
    const int kg = wid >> 3;
    const int wy = wid & 3, wx = (wid >> 2) & 1;
    wmma::fragment<wmma::accumulator, 16, 16, 16, float> c00, c01, c10, c11;
    wmma::fill_fragment(c00, 0.f);
    wmma::fill_fragment(c01, 0.f);
    wmma::fill_fragment(c10, 0.f);
    wmma::fill_fragment(c11, 0.f);

    float dsum = 0.f;

    // prologue: prefetch tile 0 (B, mask) + stage sFF[0], prefetch ffh tile 1
    uint4 nbg0 = *(const uint4*)bsrc;
    uint4 nbg1 = *(const uint4*)(bsrc + 16);
    unsigned nmw = mrow[q];
    uint4 nffu;
    if (tid < 32) {
        *(uint4*)(sFF[0] + tid * 4) = *(const uint4*)(ffh + tid * 4);
        nffu = *(const uint4*)(ffh + TJ + tid * 4);
    }
    __syncthreads();                   // sFF[0] visible

#pragma unroll 1
    for (int jt = 0; jt < NTILE_J; ++jt) {
        const int b = jt & 1;

        // ---- STS phase: write tile jt from prefetched regs into buf[b] ----
        *(uint4*)(sB[b] + bdst)     = nbg0;
        *(uint4*)(sB[b] + bdst + 8) = nbg1;
        if (jt + 1 < NTILE_J && tid < 32)
            *(uint4*)(sFF[b ^ 1] + tid * 4) = nffu;   // ffh for tile jt+1
        {
            const unsigned mw = nmw;
            const unsigned* ffb = sFF[b] + jl0;
            unsigned pk[16];
#pragma unroll
            for (int k2 = 0; k2 < 16; ++k2) {
                const uint2 ww = *(const uint2*)(ffb + 2 * k2);
                // pre-mask: zero packed {F1,F2} when edge absent (=> p = 0)
                const unsigned w0 = (mw & (1u << (2 * k2)))     ? ww.x : 0u;
                const unsigned w1 = (mw & (2u << (2 * k2)))     ? ww.y : 0u;
                const unsigned m0 = mul_bf16x2(w0, epk);   // {e1F1_0, e2F2_0}
                const unsigned m1 = mul_bf16x2(w1, epk);   // {e1F1_1, e2F2_1}
                const unsigned lo = __byte_perm(m0, m1, 0x5410); // {e1F1_0, e1F1_1}
                const unsigned hi = __byte_perm(m0, m1, 0x7632); // {e2F2_0, e2F2_1}
                const unsigned p  = max_bf16x2(lo, hi);          // {p0, p1}
                dsum += __uint_as_float(p << 16)
                      + __uint_as_float(p & 0xFFFF0000u);
                pk[k2] = p;
            }
            uint4* d = (uint4*)(sP[b] + r * PSTR + jl0);
            d[0] = make_uint4(pk[0],  pk[1],  pk[2],  pk[3]);
            d[1] = make_uint4(pk[4],  pk[5],  pk[6],  pk[7]);
            d[2] = make_uint4(pk[8],  pk[9],  pk[10], pk[11]);
            d[3] = make_uint4(pk[12], pk[13], pk[14], pk[15]);
        }

        // ---- prefetch tile jt+1 (B, mask) and tile jt+2 (ffh) ----
        if (jt + 1 < NTILE_J) {
            const int jb = (jt + 1) * TJ;
            nbg0 = *(const uint4*)(bsrc + jb * 2);
            nbg1 = *(const uint4*)(bsrc + jb * 2 + 16);
            nmw = mrow[(jt + 1) * 4 + q];
            if (jt + 2 < NTILE_J && tid < 32)
                nffu = *(const uint4*)(ffh + (jt + 2) * TJ + tid * 4);
        }

        __syncthreads();               // buf[b] complete; prior compute drained

        // ---- compute(jt) from buf[b]: this warp's 4 k-steps ----
#pragma unroll
        for (int ks = 0; ks < 4; ++ks) {
            const int k = kg * 4 + ks;
            wmma::fragment<wmma::matrix_a, 16, 16, 16, __nv_bfloat16, wmma::row_major> aL, aH;
            wmma::fragment<wmma::matrix_b, 16, 16, 16, __nv_bfloat16, wmma::col_major> b0, b1;
            wmma::load_matrix_sync(aL, sP[b] + (wy * 32) * PSTR + k * 16, PSTR);
            wmma::load_matrix_sync(aH, sP[b] + (wy * 32 + 16) * PSTR + k * 16, PSTR);
            wmma::load_matrix_sync(b0, sB[b] + (wx * 32) * PSTR + k * 16, PSTR);
            wmma::load_matrix_sync(b1, sB[b] + (wx * 32 + 16) * PSTR + k * 16, PSTR);
            wmma::mma_sync(c00, aL, b0, c00);
            wmma::mma_sync(c01, aL, b1, c01);
            wmma::mma_sync(c10, aH, b0, c10);
            wmma::mma_sync(c11, aH, b1, c11);
        }
    }

    sDen[q][r] = dsum;
    __syncthreads();                   // mainloop fully done; safe to alias

    // store partial C per k-group, then merge in the final epilogue
    {
        float* dst = (kg == 0) ? sCa : sCb;
        const int rb = wy * 32, cb = wx * 32;
        wmma::store_matrix_sync(dst + rb * CSTR + cb,               c00, CSTR, wmma::mem_row_major);
        wmma::store_matrix_sync(dst + rb * CSTR + cb + 16,          c01, CSTR, wmma::mem_row_major);
        wmma::store_matrix_sync(dst + (rb + 16) * CSTR + cb,        c10, CSTR, wmma::mem_row_major);
        wmma::store_matrix_sync(dst + (rb + 16) * CSTR + cb + 16,   c11, CSTR, wmma::mem_row_major);
    }
    __syncthreads();

    // epilogue: merge k-groups, normalize, ELU, write
    const int row = tid >> 2, cg = tid & 3;
    if (i0 + row < NTOT) {
        const float den = sDen[0][row] + sDen[1][row] + sDen[2][row] + sDen[3][row];
        const float inv = 1.f / den;
        const float* sa = sCa + row * CSTR + cg * 16;
        const float* sb = sCb + row * CSTR + cg * 16;
        float* op = g_x2 + (i0 + row) * (HEADS * OUT_F) + head * OUT_F + cg * 16;
#pragma unroll
        for (int c4 = 0; c4 < 4; ++c4) {
            float4 va = *(const float4*)(sa + c4 * 4);
            float4 vb = *(const float4*)(sb + c4 * 4);
            float x0 = (va.x + vb.x) * inv, x1 = (va.y + vb.y) * inv;
            float x2 = (va.z + vb.z) * inv, x3 = (va.w + vb.w) * inv;
            x0 = (x0 > 0.f) ? x0 : expm1f(x0);
            x1 = (x1 > 0.f) ? x1 : expm1f(x1);
            x2 = (x2 > 0.f) ? x2 : expm1f(x2);
            x3 = (x3 > 0.f) ? x3 : expm1f(x3);
            *(float4*)(op + c4 * 4) = make_float4(x0, x1, x2, x3);
        }
    }
}

// ---------------- kernel 5: log_softmax (128-wide) + permuted row write ----------------
__global__ void __launch_bounds__(256) k_lsm(float* __restrict__ out) {
    const int lane = threadIdx.x & 31;
    const int i = blockIdx.x * 8 + (threadIdx.x >> 5);
    float4 v = ((const float4*)(g_x2 + i * 128))[lane];
    float mx = fmaxf(fmaxf(v.x, v.y), fmaxf(v.z, v.w));
#pragma unroll
    for (int off = 16; off > 0; off >>= 1)
        mx = fmaxf(mx, __shfl_xor_sync(0xffffffffu, mx, off));
    float sum = __expf(v.x - mx) + __expf(v.y - mx) + __expf(v.z - mx) + __expf(v.w - mx);
#pragma unroll
    for (int off = 16; off > 0; off >>= 1)
        sum += __shfl_xor_sync(0xffffffffu, sum, off);
    const float lse = mx + logf(sum);
    const int orow = (i < N1 + N2) ? (i + N3) : (i - (N1 + N2));
    float4 o = make_float4(v.x - lse, v.y - lse, v.z - lse, v.w - lse);
    ((float4*)out)[orow * 32 + lane] = o;
}

// ---------------- launch ----------------
// Order keeps k_att at ncu launch index 3 (-s 5 -c 1 profiles index 3).
extern "C" void kernel_launch(void* const* d_in, const int* in_sizes, int n_in,
                              void* d_out, int out_size) {
    const float* h   = (const float*)d_in[0];
    const int*   A1  = (const int*)d_in[1];
    const int*   A2  = (const int*)d_in[2];
    const int*   A3  = (const int*)d_in[3];
    const int*   A12 = (const int*)d_in[4];
    const int*   A13 = (const int*)d_in[5];
    const int*   A23 = (const int*)d_in[6];
    const int*   A21 = (const int*)d_in[7];
    const int*   A31 = (const int*)d_in[8];
    const int*   A32 = (const int*)d_in[9];
    const float* Ws  = (const float*)d_in[10];
    const float* ap  = (const float*)d_in[11];

    const int wh_smem = (128 * 68 + 128 * 128) * sizeof(float);   // 100352
    cudaFuncSetAttribute(k_wh,  cudaFuncAttributeMaxDynamicSharedMemorySize, wh_smem);
    cudaFuncSetAttribute(k_att, cudaFuncAttributeMaxDynamicSharedMemorySize, ATT_SMEM);

    k_maskpack<<<NTOT, 256>>>(A1, A2, A3, A12, A13, A23, A21, A31, A32);
    k_scal<<<(HEADS * NTOT + 255) / 256, 256>>>(h, Ws, ap);
    k_wh<<<NTOT / 64, 256, wh_smem>>>(h, Ws);
    k_att<<<dim3(IBLK, HEADS), 512, ATT_SMEM>>>();
    k_lsm<<<NTOT / 8, 256>>>((float*)d_out);
}